// round 7
// baseline (speedup 1.0000x reference)
#include <cuda_runtime.h>
#include <math.h>
#include <stdint.h>

// Problem constants
#define BB   8
#define TT   512
#define DD   128
#define DLL  16
#define KK   8
#define HTH  32
#define NROWS (BB*TT)   // 4096
#define EPS2 0.0001f

// gelu Taylor: gelu(x) = 0.5x + C0 x^2 + C1 x^4 (|x| small)
#define C0g  0.3989422804014327f
#define C1g  (-0.06649038006690545f)

// Phi LUT: 2048 entries over dl2 in [0,16), step 1/128
#define LUTN   2048
#define LUTSCL 128.0f

// Scratch
__device__ __align__(16) float  g_l[2][NROWS*DLL];   // projected l vectors
__device__ __align__(16) float  g_PQ[2][NROWS*HTH];  // theta rank-1 vectors
__device__ float  g_hn[2][NROWS];
__device__ float  g_ln[2][NROWS];
__device__ float  g_c[2][NROWS];
__device__ __align__(16) float2 g_lut[LUTN];

// packed dual fp32 fma (sm_103a FFMA2)
#define FMA2(acc, av, bv) \
    asm("fma.rn.f32x2 %0, %1, %2, %0;" : "+l"(acc) : "l"(av), "l"(bv))

__device__ __forceinline__ float hsum2(unsigned long long v) {
    float lo, hi;
    asm("mov.b64 {%0,%1}, %2;" : "=f"(lo), "=f"(hi) : "l"(v));
    return lo + hi;
}

__device__ __forceinline__ float gelu_exact(float x) {
    return 0.5f * x * (1.0f + erff(x * 0.7071067811865475f));
}

// ---------------------------------------------------------------------------
// prep: grid (64, 3), block 128, dynamic smem.  (unchanged from R6)
// ---------------------------------------------------------------------------
#define P_SROW 0                       // 64 x 132
#define P_SWT  (P_SROW + 64*132)       // 24 x 132 (transposed weights)
#define P_SL   (P_SWT  + 24*132)       // 64 x 20
#define P_STH  (P_SL   + 64*20)        // 64 x 12
#define P_SCW  (P_STH  + 64*12)        // 8 x 32
#define PREP_SMEM ((P_SCW + 256) * 4)

__global__ __launch_bounds__(128)
void prep_kernel(const float* __restrict__ h,
                 const float* __restrict__ hsrc,
                 const float* __restrict__ W_l,
                 const float* __restrict__ W_theta,
                 const float* __restrict__ wq,
                 const float* __restrict__ ws,
                 const float* __restrict__ wd,
                 const float* __restrict__ b1,
                 const float* __restrict__ w2_w,
                 const float* __restrict__ phi1_w,
                 const float* __restrict__ phi1_b,
                 const float* __restrict__ phi2_w,
                 const float* __restrict__ phi2_b)
{
    int side = blockIdx.y;
    int tid  = threadIdx.x;

    if (side == 2) {
        int wid = tid >> 5, lane = tid & 31;
        float w = phi1_w[lane], b = phi1_b[lane], v = phi2_w[lane];
        float ph2b = phi2_b[0];
        #pragma unroll
        for (int sub = 0; sub < 8; sub++) {
            int e = blockIdx.x * 32 + wid * 8 + sub;
            float x0 = (float)e       * (1.0f / LUTSCL);
            float x1 = (float)(e + 1) * (1.0f / LUTSCL);
            float s0 = gelu_exact(fmaf(x0, w, b)) * v;
            float s1 = gelu_exact(fmaf(x1, w, b)) * v;
            #pragma unroll
            for (int o = 16; o > 0; o >>= 1) {
                s0 += __shfl_xor_sync(0xffffffffu, s0, o);
                s1 += __shfl_xor_sync(0xffffffffu, s1, o);
            }
            if (lane == 0) {
                float a0 = s0 + ph2b, a1 = s1 + ph2b;
                float c0 = fmaxf(a0, 0.f) + log1pf(expf(-fabsf(a0)));
                float c1 = fmaxf(a1, 0.f) + log1pf(expf(-fabsf(a1)));
                float p0 = expf(-c0 * x0);
                float p1 = expf(-c1 * x1);
                g_lut[e] = make_float2(p0, p1 - p0);
            }
        }
        return;
    }

    extern __shared__ float ps[];
    float* SROW = ps + P_SROW;
    float* SWT  = ps + P_SWT;
    float* SL   = ps + P_SL;
    float* STH  = ps + P_STH;
    float* SCW  = ps + P_SCW;

    int r0 = blockIdx.x * 64;
    const float* src = (side == 0) ? h : hsrc;

    {
        const float4* sv = (const float4*)(src + (size_t)r0 * DD);
        #pragma unroll
        for (int i = 0; i < 16; i++) {
            int idx = tid + i * 128;
            int r = idx >> 5, c4 = idx & 31;
            *(float4*)(SROW + r * 132 + c4 * 4) = sv[r * 32 + c4];
        }
        #pragma unroll
        for (int i = 0; i < 16; i++) {
            int idx = tid + i * 128;
            int c = idx & 15, d = idx >> 4;
            SWT[c * 132 + d] = W_l[d * DLL + c];
        }
        #pragma unroll
        for (int i = 0; i < 8; i++) {
            int idx = tid + i * 128;
            int c = idx & 7, d = idx >> 3;
            SWT[(16 + c) * 132 + d] = W_theta[d * KK + c];
        }
        #pragma unroll
        for (int i = 0; i < 2; i++) {
            int idx = tid + i * 128;
            float a = wq[idx], s = ws[idx], d = wd[idx];
            SCW[idx] = (side == 0) ? (a + d) : (s - d);
        }
    }
    __syncthreads();

    {
        int rg = tid >> 3, cg = tid & 7;
        float acc[4][3];
        #pragma unroll
        for (int i = 0; i < 4; i++)
            #pragma unroll
            for (int j = 0; j < 3; j++) acc[i][j] = 0.f;

        const float* sr = SROW + (rg * 4) * 132;
        #pragma unroll 4
        for (int kc = 0; kc < 32; kc++) {
            float4 x[4], w[3];
            #pragma unroll
            for (int i = 0; i < 4; i++)
                x[i] = *(const float4*)(sr + i * 132 + kc * 4);
            #pragma unroll
            for (int j = 0; j < 3; j++)
                w[j] = *(const float4*)(SWT + (cg + 8 * j) * 132 + kc * 4);
            #pragma unroll
            for (int i = 0; i < 4; i++)
                #pragma unroll
                for (int j = 0; j < 3; j++) {
                    acc[i][j] = fmaf(x[i].x, w[j].x, acc[i][j]);
                    acc[i][j] = fmaf(x[i].y, w[j].y, acc[i][j]);
                    acc[i][j] = fmaf(x[i].z, w[j].z, acc[i][j]);
                    acc[i][j] = fmaf(x[i].w, w[j].w, acc[i][j]);
                }
        }
        #pragma unroll
        for (int i = 0; i < 4; i++)
            #pragma unroll
            for (int j = 0; j < 3; j++) {
                int r = rg * 4 + i, c = cg + 8 * j;
                if (c < DLL) {
                    SL[r * 20 + c] = acc[i][j];
                    g_l[side][(size_t)(r0 + r) * DLL + c] = acc[i][j];
                } else {
                    STH[r * 12 + (c - 16)] = acc[i][j];
                }
            }
    }
    __syncthreads();

    {
        int r = tid >> 1, half = tid & 1;
        const float* sr = SROW + r * 132 + half * 64;
        float a = 0.f;
        #pragma unroll
        for (int c4 = 0; c4 < 16; c4++) {
            float4 x = *(const float4*)(sr + c4 * 4);
            a = fmaf(x.x, x.x, a); a = fmaf(x.y, x.y, a);
            a = fmaf(x.z, x.z, a); a = fmaf(x.w, x.w, a);
        }
        a += __shfl_xor_sync(0xffffffffu, a, 1);
        if (half == 0) g_hn[side][r0 + r] = a;
    }
    if (tid < 64) {
        const float* sr = SL + tid * 20;
        float a = 0.f;
        #pragma unroll
        for (int c4 = 0; c4 < 4; c4++) {
            float4 x = *(const float4*)(sr + c4 * 4);
            a = fmaf(x.x, x.x, a); a = fmaf(x.y, x.y, a);
            a = fmaf(x.z, x.z, a); a = fmaf(x.w, x.w, a);
        }
        g_ln[side][r0 + tid] = a;
    }

    #pragma unroll
    for (int i = 0; i < 16; i++) {
        int idx = tid + i * 128;
        int r = idx >> 5, c = idx & 31;
        float x = (side == 0) ? __ldg(&b1[c]) : 0.f;
        #pragma unroll
        for (int k = 0; k < KK; k++)
            x = fmaf(STH[r * 12 + k], SCW[k * HTH + c], x);
        float w2 = __ldg(&w2_w[c]);
        float x2 = x * x;
        g_PQ[side][(size_t)(r0 + r) * HTH + c] =
            (side == 0) ? (2.0f * C0g * w2 * x) : x;
        float v = w2 * (fmaf(C1g, x2 * x2, fmaf(C0g, x2, 0.5f * x)));
        #pragma unroll
        for (int o = 16; o > 0; o >>= 1)
            v += __shfl_xor_sync(0xffffffffu, v, o);
        if (c == 0) g_c[side][r0 + r] = v;
    }
}

// ---------------------------------------------------------------------------
// Kernel A: tp = -Theta * Phi  ->  out.
// 128x128 tile, 256 thr, 8x8 micro-tile done in two j-halves (8x4 each).
// ---------------------------------------------------------------------------
#define A_SPT 0
#define A_SQS (A_SPT + 128*36)
#define A_SLT (A_SQS + 128*36)
#define A_SLS (A_SLT + 128*20)
#define A_SC  (A_SLS + 128*20)     // [0]=ln_t [128]=ln_s [256]=c_t [384]=c_s
#define A_SMEM ((A_SC + 512) * 4)

__global__ __launch_bounds__(256, 1)
void kernelA(const float* __restrict__ w2_b, float* __restrict__ out)
{
    extern __shared__ float sa[];
    float* Pt = sa + A_SPT;     // stride 36
    float* Qs = sa + A_SQS;
    float* Lt = sa + A_SLT;     // stride 20
    float* Ls = sa + A_SLS;
    float* sc = sa + A_SC;

    int bz  = blockIdx.z;
    int t0  = blockIdx.y * 128;
    int s0  = blockIdx.x * 128;
    int tid = threadIdx.x;
    int rt  = bz * TT + t0;
    int rs  = bz * TT + s0;

    // --- stage ---
    {
        const float4* pt = (const float4*)(g_PQ[0] + (size_t)rt * HTH);
        const float4* qs = (const float4*)(g_PQ[1] + (size_t)rs * HTH);
        #pragma unroll
        for (int i = 0; i < 4; i++) {
            int idx = tid + i * 256;        // < 1024
            int r = idx >> 3, c4 = idx & 7;
            *(float4*)(Pt + r * 36 + c4 * 4) = pt[r * 8 + c4];
            *(float4*)(Qs + r * 36 + c4 * 4) = qs[r * 8 + c4];
        }
        const float4* lt = (const float4*)(g_l[0] + (size_t)rt * DLL);
        const float4* ls = (const float4*)(g_l[1] + (size_t)rs * DLL);
        #pragma unroll
        for (int i = 0; i < 2; i++) {
            int idx = tid + i * 256;        // < 512
            int r = idx >> 2, c4 = idx & 3;
            *(float4*)(Lt + r * 20 + c4 * 4) = lt[r * 4 + c4];
            *(float4*)(Ls + r * 20 + c4 * 4) = ls[r * 4 + c4];
        }
        if (tid < 128) {
            sc[tid]       = g_ln[0][rt + tid];
            sc[128 + tid] = g_ln[1][rs + tid];
            sc[256 + tid] = g_c [0][rt + tid];
            sc[384 + tid] = g_c [1][rs + tid];
        }
    }
    float w2b = __ldg(w2_b);
    __syncthreads();

    int tx = tid & 15, ty = tid >> 4;
    size_t ob = ((size_t)(bz * TT + t0)) * TT + s0;

    #pragma unroll
    for (int jh = 0; jh < 2; jh++) {
        unsigned long long acc[32];
        float tp[32];

        // ---- theta dot: K=32 -> 8 f4-iters ----
        #pragma unroll
        for (int q = 0; q < 32; q++) acc[q] = 0ull;
        #pragma unroll
        for (int k4 = 0; k4 < 8; k4++) {
            ulonglong2 a[8];
            #pragma unroll
            for (int i = 0; i < 8; i++)
                a[i] = *(const ulonglong2*)(Pt + (ty + 16 * i) * 36 + k4 * 4);
            #pragma unroll
            for (int jj = 0; jj < 4; jj++) {
                int col = tx + 16 * (4 * jh + jj);
                ulonglong2 b = *(const ulonglong2*)(Qs + col * 36 + k4 * 4);
                #pragma unroll
                for (int i = 0; i < 8; i++) {
                    FMA2(acc[i * 4 + jj], a[i].x, b.x);
                    FMA2(acc[i * 4 + jj], a[i].y, b.y);
                }
            }
        }
        #pragma unroll
        for (int i = 0; i < 8; i++) {
            float ct = sc[256 + ty + 16 * i];
            #pragma unroll
            for (int jj = 0; jj < 4; jj++) {
                float a = w2b + ct + sc[384 + tx + 16 * (4 * jh + jj)]
                          + hsum2(acc[i * 4 + jj]);
                float u = a * a;
                float Th = a * fmaf(u, fmaf(u, fmaf(u, -0.05396825397f,
                                                    0.13333333333f),
                                            -0.33333333333f), 1.0f);
                tp[i * 4 + jj] = -Th;
            }
        }

        // ---- l dot: K=16 -> 4 f4-iters -> Phi ----
        #pragma unroll
        for (int q = 0; q < 32; q++) acc[q] = 0ull;
        #pragma unroll
        for (int k4 = 0; k4 < 4; k4++) {
            ulonglong2 a[8];
            #pragma unroll
            for (int i = 0; i < 8; i++)
                a[i] = *(const ulonglong2*)(Lt + (ty + 16 * i) * 20 + k4 * 4);
            #pragma unroll
            for (int jj = 0; jj < 4; jj++) {
                int col = tx + 16 * (4 * jh + jj);
                ulonglong2 b = *(const ulonglong2*)(Ls + col * 20 + k4 * 4);
                #pragma unroll
                for (int i = 0; i < 8; i++) {
                    FMA2(acc[i * 4 + jj], a[i].x, b.x);
                    FMA2(acc[i * 4 + jj], a[i].y, b.y);
                }
            }
        }
        #pragma unroll
        for (int i = 0; i < 8; i++) {
            float lnt = sc[ty + 16 * i];
            size_t orow = ob + (size_t)(ty + 16 * i) * TT;
            #pragma unroll
            for (int jj = 0; jj < 4; jj++) {
                int col = tx + 16 * (4 * jh + jj);
                float e   = hsum2(acc[i * 4 + jj]);
                float dl2 = fmaxf(fmaf(-2.f, e, lnt + sc[128 + col]), 0.f);
                float t   = fminf(dl2 * LUTSCL, (float)(LUTN - 1));
                int   ix  = (int)t;
                float fr  = t - (float)ix;
                float2 lv = __ldg(&g_lut[ix]);
                out[orow + col] = tp[i * 4 + jj] * fmaf(fr, lv.y, lv.x);
            }
        }
    }
}

// ---------------------------------------------------------------------------
// Kernel B: pure K=128 Gram GEMM; out *= 1/r.
// 128x128 tile, 256 thr, 8x8 micro-tile, acc[64] ull, f4 loads.
// ---------------------------------------------------------------------------
#define B_SHT 0
#define B_SHS (B_SHT + 128*132)
#define B_SC  (B_SHS + 128*132)    // [0]=hn_t [128]=hn_s
#define B_SMEM ((B_SC + 256) * 4)

__global__ __launch_bounds__(256, 1)
void kernelB(const float* __restrict__ h, const float* __restrict__ hsrc,
             float* __restrict__ out)
{
    extern __shared__ float sb[];
    float* Ht = sb + B_SHT;     // stride 132
    float* Hs = sb + B_SHS;
    float* sc = sb + B_SC;

    int bz  = blockIdx.z;
    int t0  = blockIdx.y * 128;
    int s0  = blockIdx.x * 128;
    int tid = threadIdx.x;
    int rt  = bz * TT + t0;
    int rs  = bz * TT + s0;

    {
        const float4* tv = (const float4*)(h    + (size_t)rt * DD);
        const float4* sv = (const float4*)(hsrc + (size_t)rs * DD);
        #pragma unroll
        for (int i = 0; i < 16; i++) {
            int idx = tid + i * 256;        // < 4096
            int r = idx >> 5, c4 = idx & 31;
            *(float4*)(Ht + r * 132 + c4 * 4) = tv[r * 32 + c4];
            *(float4*)(Hs + r * 132 + c4 * 4) = sv[r * 32 + c4];
        }
        if (tid < 128) {
            sc[tid]       = g_hn[0][rt + tid];
            sc[128 + tid] = g_hn[1][rs + tid];
        }
    }
    __syncthreads();

    int tx = tid & 15, ty = tid >> 4;

    unsigned long long acc[64];
    #pragma unroll
    for (int q = 0; q < 64; q++) acc[q] = 0ull;

    #pragma unroll 4
    for (int k4 = 0; k4 < 32; k4++) {          // K=128 floats
        ulonglong2 a[8];
        #pragma unroll
        for (int i = 0; i < 8; i++)
            a[i] = *(const ulonglong2*)(Ht + (ty + 16 * i) * 132 + k4 * 4);
        #pragma unroll
        for (int j = 0; j < 8; j++) {
            ulonglong2 b = *(const ulonglong2*)(Hs + (tx + 16 * j) * 132 + k4 * 4);
            #pragma unroll
            for (int i = 0; i < 8; i++) {
                FMA2(acc[i * 8 + j], a[i].x, b.x);
                FMA2(acc[i * 8 + j], a[i].y, b.y);
            }
        }
    }

    {
        size_t ob = ((size_t)(bz * TT + t0)) * TT + s0 + tx;
        #pragma unroll
        for (int i = 0; i < 8; i++) {
            float hnt = sc[ty + 16 * i];
            size_t orow = ob + (size_t)(ty + 16 * i) * TT;
            float tpv[8];
            #pragma unroll
            for (int j = 0; j < 8; j++) tpv[j] = out[orow + 16 * j];
            #pragma unroll
            for (int j = 0; j < 8; j++) {
                float d   = hsum2(acc[i * 8 + j]);
                float dh2 = fmaxf(fmaf(-2.f, d, hnt + sc[128 + tx + 16 * j]), 0.f)
                            + EPS2;
                out[orow + 16 * j] = tpv[j] * rsqrtf(dh2);
            }
        }
    }
}

// ---------------------------------------------------------------------------
extern "C" void kernel_launch(void* const* d_in, const int* in_sizes, int n_in,
                              void* d_out, int out_size)
{
    (void)in_sizes; (void)n_in; (void)out_size;
    const float* h       = (const float*)d_in[0];
    const float* hsrc    = (const float*)d_in[1];
    const float* W_l     = (const float*)d_in[2];
    const float* W_theta = (const float*)d_in[3];
    const float* phi1_w  = (const float*)d_in[4];
    const float* phi1_b  = (const float*)d_in[5];
    const float* phi2_w  = (const float*)d_in[6];
    const float* phi2_b  = (const float*)d_in[7];
    const float* wq      = (const float*)d_in[8];
    const float* ws      = (const float*)d_in[9];
    const float* wd      = (const float*)d_in[10];
    const float* b1      = (const float*)d_in[11];
    const float* w2_w    = (const float*)d_in[12];
    const float* w2_b    = (const float*)d_in[13];
    float* out = (float*)d_out;

    cudaFuncSetAttribute(prep_kernel,
                         cudaFuncAttributeMaxDynamicSharedMemorySize, PREP_SMEM);
    cudaFuncSetAttribute(kernelA,
                         cudaFuncAttributeMaxDynamicSharedMemorySize, A_SMEM);
    cudaFuncSetAttribute(kernelB,
                         cudaFuncAttributeMaxDynamicSharedMemorySize, B_SMEM);

    prep_kernel<<<dim3(64, 3), 128, PREP_SMEM>>>(h, hsrc, W_l, W_theta,
                                                 wq, ws, wd, b1, w2_w,
                                                 phi1_w, phi1_b, phi2_w, phi2_b);
    kernelA<<<dim3(4, 4, BB), 256, A_SMEM>>>(w2_b, out);
    kernelB<<<dim3(4, 4, BB), 256, B_SMEM>>>(h, hsrc, out);
}

// round 8
// speedup vs baseline: 1.1554x; 1.1554x over previous
#include <cuda_runtime.h>
#include <math.h>
#include <stdint.h>

// Problem constants
#define BB   8
#define TT   512
#define DD   128
#define DLL  16
#define KK   8
#define HTH  32
#define NROWS (BB*TT)   // 4096
#define EPS2 0.0001f

// gelu Taylor: gelu(x) = 0.5x + C0 x^2 + C1 x^4 (|x| small)
#define C0g  0.3989422804014327f
#define C1g  (-0.06649038006690545f)

// Phi LUT: 2048 entries over dl2 in [0,16), step 1/128
#define LUTN   2048
#define LUTSCL 128.0f

// Scratch
__device__ __align__(16) float  g_l[2][NROWS*DLL];   // projected l vectors
__device__ __align__(16) float  g_PQ[2][NROWS*HTH];  // theta rank-1 vectors
__device__ float  g_hn[2][NROWS];
__device__ float  g_ln[2][NROWS];
__device__ float  g_c[2][NROWS];
__device__ __align__(16) float2 g_lut[LUTN];

// packed dual fp32 fma (sm_103a FFMA2)
#define FMA2(acc, av, bv) \
    asm("fma.rn.f32x2 %0, %1, %2, %0;" : "+l"(acc) : "l"(av), "l"(bv))

__device__ __forceinline__ float hsum2(unsigned long long v) {
    float lo, hi;
    asm("mov.b64 {%0,%1}, %2;" : "=f"(lo), "=f"(hi) : "l"(v));
    return lo + hi;
}

__device__ __forceinline__ float gelu_exact(float x) {
    return 0.5f * x * (1.0f + erff(x * 0.7071067811865475f));
}

// ---------------------------------------------------------------------------
// prep: grid (64, 3), block 128, dynamic smem.  (R6 version — measured ~4us)
// ---------------------------------------------------------------------------
#define P_SROW 0                       // 64 x 132
#define P_SWT  (P_SROW + 64*132)       // 24 x 132 (transposed weights)
#define P_SL   (P_SWT  + 24*132)       // 64 x 20
#define P_STH  (P_SL   + 64*20)        // 64 x 12
#define P_SCW  (P_STH  + 64*12)        // 8 x 32
#define PREP_SMEM ((P_SCW + 256) * 4)

__global__ __launch_bounds__(128)
void prep_kernel(const float* __restrict__ h,
                 const float* __restrict__ hsrc,
                 const float* __restrict__ W_l,
                 const float* __restrict__ W_theta,
                 const float* __restrict__ wq,
                 const float* __restrict__ ws,
                 const float* __restrict__ wd,
                 const float* __restrict__ b1,
                 const float* __restrict__ w2_w,
                 const float* __restrict__ phi1_w,
                 const float* __restrict__ phi1_b,
                 const float* __restrict__ phi2_w,
                 const float* __restrict__ phi2_b)
{
    int side = blockIdx.y;
    int tid  = threadIdx.x;

    if (side == 2) {
        int wid = tid >> 5, lane = tid & 31;
        float w = phi1_w[lane], b = phi1_b[lane], v = phi2_w[lane];
        float ph2b = phi2_b[0];
        #pragma unroll
        for (int sub = 0; sub < 8; sub++) {
            int e = blockIdx.x * 32 + wid * 8 + sub;
            float x0 = (float)e       * (1.0f / LUTSCL);
            float x1 = (float)(e + 1) * (1.0f / LUTSCL);
            float s0 = gelu_exact(fmaf(x0, w, b)) * v;
            float s1 = gelu_exact(fmaf(x1, w, b)) * v;
            #pragma unroll
            for (int o = 16; o > 0; o >>= 1) {
                s0 += __shfl_xor_sync(0xffffffffu, s0, o);
                s1 += __shfl_xor_sync(0xffffffffu, s1, o);
            }
            if (lane == 0) {
                float a0 = s0 + ph2b, a1 = s1 + ph2b;
                float c0 = fmaxf(a0, 0.f) + log1pf(expf(-fabsf(a0)));
                float c1 = fmaxf(a1, 0.f) + log1pf(expf(-fabsf(a1)));
                float p0 = expf(-c0 * x0);
                float p1 = expf(-c1 * x1);
                g_lut[e] = make_float2(p0, p1 - p0);
            }
        }
        return;
    }

    extern __shared__ float ps[];
    float* SROW = ps + P_SROW;
    float* SWT  = ps + P_SWT;
    float* SL   = ps + P_SL;
    float* STH  = ps + P_STH;
    float* SCW  = ps + P_SCW;

    int r0 = blockIdx.x * 64;
    const float* src = (side == 0) ? h : hsrc;

    {
        const float4* sv = (const float4*)(src + (size_t)r0 * DD);
        #pragma unroll
        for (int i = 0; i < 16; i++) {
            int idx = tid + i * 128;
            int r = idx >> 5, c4 = idx & 31;
            *(float4*)(SROW + r * 132 + c4 * 4) = sv[r * 32 + c4];
        }
        #pragma unroll
        for (int i = 0; i < 16; i++) {
            int idx = tid + i * 128;
            int c = idx & 15, d = idx >> 4;
            SWT[c * 132 + d] = W_l[d * DLL + c];
        }
        #pragma unroll
        for (int i = 0; i < 8; i++) {
            int idx = tid + i * 128;
            int c = idx & 7, d = idx >> 3;
            SWT[(16 + c) * 132 + d] = W_theta[d * KK + c];
        }
        #pragma unroll
        for (int i = 0; i < 2; i++) {
            int idx = tid + i * 128;
            float a = wq[idx], s = ws[idx], d = wd[idx];
            SCW[idx] = (side == 0) ? (a + d) : (s - d);
        }
    }
    __syncthreads();

    {
        int rg = tid >> 3, cg = tid & 7;
        float acc[4][3];
        #pragma unroll
        for (int i = 0; i < 4; i++)
            #pragma unroll
            for (int j = 0; j < 3; j++) acc[i][j] = 0.f;

        const float* sr = SROW + (rg * 4) * 132;
        #pragma unroll 4
        for (int kc = 0; kc < 32; kc++) {
            float4 x[4], w[3];
            #pragma unroll
            for (int i = 0; i < 4; i++)
                x[i] = *(const float4*)(sr + i * 132 + kc * 4);
            #pragma unroll
            for (int j = 0; j < 3; j++)
                w[j] = *(const float4*)(SWT + (cg + 8 * j) * 132 + kc * 4);
            #pragma unroll
            for (int i = 0; i < 4; i++)
                #pragma unroll
                for (int j = 0; j < 3; j++) {
                    acc[i][j] = fmaf(x[i].x, w[j].x, acc[i][j]);
                    acc[i][j] = fmaf(x[i].y, w[j].y, acc[i][j]);
                    acc[i][j] = fmaf(x[i].z, w[j].z, acc[i][j]);
                    acc[i][j] = fmaf(x[i].w, w[j].w, acc[i][j]);
                }
        }
        #pragma unroll
        for (int i = 0; i < 4; i++)
            #pragma unroll
            for (int j = 0; j < 3; j++) {
                int r = rg * 4 + i, c = cg + 8 * j;
                if (c < DLL) {
                    SL[r * 20 + c] = acc[i][j];
                    g_l[side][(size_t)(r0 + r) * DLL + c] = acc[i][j];
                } else {
                    STH[r * 12 + (c - 16)] = acc[i][j];
                }
            }
    }
    __syncthreads();

    {
        int r = tid >> 1, half = tid & 1;
        const float* sr = SROW + r * 132 + half * 64;
        float a = 0.f;
        #pragma unroll
        for (int c4 = 0; c4 < 16; c4++) {
            float4 x = *(const float4*)(sr + c4 * 4);
            a = fmaf(x.x, x.x, a); a = fmaf(x.y, x.y, a);
            a = fmaf(x.z, x.z, a); a = fmaf(x.w, x.w, a);
        }
        a += __shfl_xor_sync(0xffffffffu, a, 1);
        if (half == 0) g_hn[side][r0 + r] = a;
    }
    if (tid < 64) {
        const float* sr = SL + tid * 20;
        float a = 0.f;
        #pragma unroll
        for (int c4 = 0; c4 < 4; c4++) {
            float4 x = *(const float4*)(sr + c4 * 4);
            a = fmaf(x.x, x.x, a); a = fmaf(x.y, x.y, a);
            a = fmaf(x.z, x.z, a); a = fmaf(x.w, x.w, a);
        }
        g_ln[side][r0 + tid] = a;
    }

    #pragma unroll
    for (int i = 0; i < 16; i++) {
        int idx = tid + i * 128;
        int r = idx >> 5, c = idx & 31;
        float x = (side == 0) ? __ldg(&b1[c]) : 0.f;
        #pragma unroll
        for (int k = 0; k < KK; k++)
            x = fmaf(STH[r * 12 + k], SCW[k * HTH + c], x);
        float w2 = __ldg(&w2_w[c]);
        float x2 = x * x;
        g_PQ[side][(size_t)(r0 + r) * HTH + c] =
            (side == 0) ? (2.0f * C0g * w2 * x) : x;
        float v = w2 * (fmaf(C1g, x2 * x2, fmaf(C0g, x2, 0.5f * x)));
        #pragma unroll
        for (int o = 16; o > 0; o >>= 1)
            v += __shfl_xor_sync(0xffffffffu, v, o);
        if (c == 0) g_c[side][r0 + r] = v;
    }
}

// ---------------------------------------------------------------------------
// main: 128x128 tile, 256 thr, 8x8 micro-tile. tp lives in SMEM.
// Phase A (theta+l -> tp_s) uses region X as {Pt,Qs,Lt,Ls};
// Phase B (h Gram) re-stages X as {Ht,Hs} in two K=64 halves, acc in regs.
// ---------------------------------------------------------------------------
// float offsets in dynamic smem
#define M_X    0
#define M_PT   (M_X)                 // 128*36
#define M_QS   (M_PT + 128*36)
#define M_LT   (M_QS + 128*36)       // 128*20
#define M_LS   (M_LT + 128*20)
#define M_HT   (M_X)                 // 128*68
#define M_HS   (M_HT + 128*68)
#define M_XEND (M_X + 2*128*68)      // 17408
#define M_TP   (M_XEND)              // 16384
#define M_SC   (M_TP + 16384)        // 768
#define MAIN_SMEM ((M_SC + 768) * 4)

__global__ __launch_bounds__(256, 1)
void main_kernel(const float* __restrict__ h, const float* __restrict__ hsrc,
                 const float* __restrict__ w2_b, float* __restrict__ out)
{
    extern __shared__ float S[];
    float* tp_s = S + M_TP;
    float* sc   = S + M_SC;
    // sc: [0]=hn_t [128]=hn_s [256]=ln_t [384]=ln_s [512]=c_t [640]=c_s

    int bz  = blockIdx.z;
    int t0  = blockIdx.y * 128;
    int s0  = blockIdx.x * 128;
    int tid = threadIdx.x;
    int rt  = bz * TT + t0;
    int rs  = bz * TT + s0;

    // ============== stage phase-A tiles ==============
    {
        const float4* pt = (const float4*)(g_PQ[0] + (size_t)rt * HTH);
        const float4* qs = (const float4*)(g_PQ[1] + (size_t)rs * HTH);
        #pragma unroll
        for (int i = 0; i < 4; i++) {
            int idx = tid + i * 256;        // < 1024
            int r = idx >> 3, c4 = idx & 7;
            *(float4*)(S + M_PT + r * 36 + c4 * 4) = pt[r * 8 + c4];
            *(float4*)(S + M_QS + r * 36 + c4 * 4) = qs[r * 8 + c4];
        }
        const float4* lt = (const float4*)(g_l[0] + (size_t)rt * DLL);
        const float4* ls = (const float4*)(g_l[1] + (size_t)rs * DLL);
        #pragma unroll
        for (int i = 0; i < 2; i++) {
            int idx = tid + i * 256;        // < 512
            int r = idx >> 2, c4 = idx & 3;
            *(float4*)(S + M_LT + r * 20 + c4 * 4) = lt[r * 4 + c4];
            *(float4*)(S + M_LS + r * 20 + c4 * 4) = ls[r * 4 + c4];
        }
        if (tid < 128) {
            sc[tid]       = g_hn[0][rt + tid];
            sc[128 + tid] = g_hn[1][rs + tid];
            sc[256 + tid] = g_ln[0][rt + tid];
            sc[384 + tid] = g_ln[1][rs + tid];
            sc[512 + tid] = g_c [0][rt + tid];
            sc[640 + tid] = g_c [1][rs + tid];
        }
    }
    float w2b = __ldg(w2_b);
    __syncthreads();

    int tx = tid & 15, ty = tid >> 4;

    unsigned long long acc[64];

    // ============== theta dot (K=32) -> -Theta into tp_s ==============
    #pragma unroll
    for (int q = 0; q < 64; q++) acc[q] = 0ull;
    #pragma unroll
    for (int k4 = 0; k4 < 8; k4++) {
        ulonglong2 a[8];
        #pragma unroll
        for (int i = 0; i < 8; i++)
            a[i] = *(const ulonglong2*)(S + M_PT + (ty + 16 * i) * 36 + k4 * 4);
        #pragma unroll
        for (int j = 0; j < 8; j++) {
            ulonglong2 b = *(const ulonglong2*)(S + M_QS + (tx + 16 * j) * 36 + k4 * 4);
            #pragma unroll
            for (int i = 0; i < 8; i++) {
                FMA2(acc[i * 8 + j], a[i].x, b.x);
                FMA2(acc[i * 8 + j], a[i].y, b.y);
            }
        }
    }
    #pragma unroll
    for (int i = 0; i < 8; i++) {
        float ct = sc[512 + ty + 16 * i];
        #pragma unroll
        for (int j = 0; j < 8; j++) {
            float a = w2b + ct + sc[640 + tx + 16 * j] + hsum2(acc[i * 8 + j]);
            float u = a * a;
            float Th = a * fmaf(u, fmaf(u, fmaf(u, -0.05396825397f,
                                                0.13333333333f),
                                        -0.33333333333f), 1.0f);
            tp_s[(i * 8 + j) * 256 + tid] = -Th;
        }
    }

    // ============== l dot (K=16) -> tp_s *= Phi ==============
    #pragma unroll
    for (int q = 0; q < 64; q++) acc[q] = 0ull;
    #pragma unroll
    for (int k4 = 0; k4 < 4; k4++) {
        ulonglong2 a[8];
        #pragma unroll
        for (int i = 0; i < 8; i++)
            a[i] = *(const ulonglong2*)(S + M_LT + (ty + 16 * i) * 20 + k4 * 4);
        #pragma unroll
        for (int j = 0; j < 8; j++) {
            ulonglong2 b = *(const ulonglong2*)(S + M_LS + (tx + 16 * j) * 20 + k4 * 4);
            #pragma unroll
            for (int i = 0; i < 8; i++) {
                FMA2(acc[i * 8 + j], a[i].x, b.x);
                FMA2(acc[i * 8 + j], a[i].y, b.y);
            }
        }
    }
    #pragma unroll
    for (int i = 0; i < 8; i++) {
        float lnt = sc[256 + ty + 16 * i];
        #pragma unroll
        for (int j = 0; j < 8; j++) {
            float e   = hsum2(acc[i * 8 + j]);
            float dl2 = fmaxf(fmaf(-2.f, e, lnt + sc[384 + tx + 16 * j]), 0.f);
            float t   = fminf(dl2 * LUTSCL, (float)(LUTN - 1));
            int   ix  = (int)t;
            float fr  = t - (float)ix;
            float2 lv = __ldg(&g_lut[ix]);
            tp_s[(i * 8 + j) * 256 + tid] *= fmaf(fr, lv.y, lv.x);
        }
    }

    // ============== h Gram (K=128 in two K=64 halves) ==============
    #pragma unroll
    for (int q = 0; q < 64; q++) acc[q] = 0ull;

    #pragma unroll
    for (int kh = 0; kh < 2; kh++) {
        __syncthreads();    // X region handoff (phase-A tiles dead / prev half done)
        {
            const float4* tv = (const float4*)(h    + (size_t)rt * DD + kh * 64);
            const float4* sv = (const float4*)(hsrc + (size_t)rs * DD + kh * 64);
            #pragma unroll
            for (int it = 0; it < 8; it++) {
                int idx = tid + it * 256;   // < 2048
                int r = idx >> 4, c4 = idx & 15;
                *(float4*)(S + M_HT + r * 68 + c4 * 4) = tv[r * 32 + c4];
                *(float4*)(S + M_HS + r * 68 + c4 * 4) = sv[r * 32 + c4];
            }
        }
        __syncthreads();

        #pragma unroll 4
        for (int k4 = 0; k4 < 16; k4++) {
            ulonglong2 a[8];
            #pragma unroll
            for (int i = 0; i < 8; i++)
                a[i] = *(const ulonglong2*)(S + M_HT + (ty + 16 * i) * 68 + k4 * 4);
            #pragma unroll
            for (int j = 0; j < 8; j++) {
                ulonglong2 b = *(const ulonglong2*)(S + M_HS + (tx + 16 * j) * 68 + k4 * 4);
                #pragma unroll
                for (int i = 0; i < 8; i++) {
                    FMA2(acc[i * 8 + j], a[i].x, b.x);
                    FMA2(acc[i * 8 + j], a[i].y, b.y);
                }
            }
        }
    }

    // ============== epilogue ==============
    {
        size_t ob = ((size_t)(bz * TT + t0)) * TT + s0 + tx;
        #pragma unroll
        for (int i = 0; i < 8; i++) {
            float hnt = sc[ty + 16 * i];
            size_t orow = ob + (size_t)(ty + 16 * i) * TT;
            #pragma unroll
            for (int j = 0; j < 8; j++) {
                float d   = hsum2(acc[i * 8 + j]);
                float dh2 = fmaxf(fmaf(-2.f, d, hnt + sc[128 + tx + 16 * j]), 0.f)
                            + EPS2;
                float tp  = tp_s[(i * 8 + j) * 256 + tid];
                out[orow + 16 * j] = tp * rsqrtf(dh2);
            }
        }
    }
}

// ---------------------------------------------------------------------------
extern "C" void kernel_launch(void* const* d_in, const int* in_sizes, int n_in,
                              void* d_out, int out_size)
{
    (void)in_sizes; (void)n_in; (void)out_size;
    const float* h       = (const float*)d_in[0];
    const float* hsrc    = (const float*)d_in[1];
    const float* W_l     = (const float*)d_in[2];
    const float* W_theta = (const float*)d_in[3];
    const float* phi1_w  = (const float*)d_in[4];
    const float* phi1_b  = (const float*)d_in[5];
    const float* phi2_w  = (const float*)d_in[6];
    const float* phi2_b  = (const float*)d_in[7];
    const float* wq      = (const float*)d_in[8];
    const float* ws      = (const float*)d_in[9];
    const float* wd      = (const float*)d_in[10];
    const float* b1      = (const float*)d_in[11];
    const float* w2_w    = (const float*)d_in[12];
    const float* w2_b    = (const float*)d_in[13];
    float* out = (float*)d_out;

    cudaFuncSetAttribute(prep_kernel,
                         cudaFuncAttributeMaxDynamicSharedMemorySize, PREP_SMEM);
    cudaFuncSetAttribute(main_kernel,
                         cudaFuncAttributeMaxDynamicSharedMemorySize, MAIN_SMEM);

    prep_kernel<<<dim3(64, 3), 128, PREP_SMEM>>>(h, hsrc, W_l, W_theta,
                                                 wq, ws, wd, b1, w2_w,
                                                 phi1_w, phi1_b, phi2_w, phi2_b);
    main_kernel<<<dim3(4, 4, BB), 256, MAIN_SMEM>>>(h, hsrc, w2_b, out);
}